// round 1
// baseline (speedup 1.0000x reference)
#include <cuda_runtime.h>
#include <math.h>
#include <stdint.h>

// Problem constants
#define BDIM   2
#define SLEN   2048
#define DMODEL 2048
#define NH     16
#define HD     128
#define MROWS  (BDIM * SLEN)   // 4096

// ---------------- scratch (no allocations allowed) ----------------
__device__ float g_q[(size_t)MROWS * DMODEL];    // 32 MB
__device__ float g_k[(size_t)MROWS * HD];        //  2 MB
__device__ float g_v[(size_t)MROWS * HD];        //  2 MB
__device__ float g_attn[(size_t)MROWS * DMODEL]; // 32 MB (b,h,s,hd) flat

// ---------------- GEMM: C[128x128] = A[128xK] @ W[128xK]^T + bias ----------------
#define GBM 128
#define GBN 128
#define GBK 16
#define GSTR 132   // padded stride (128+4): 2-way max smem store conflict, 16B-aligned f4 reads

__device__ __forceinline__ void gemm_tile(
    const float* __restrict__ A,     // points at row m0, lda = DMODEL
    const float* __restrict__ W,     // points at weight row n0, ldb = DMODEL
    const float* __restrict__ bias,  // points at bias[n0]
    float* __restrict__ C, int ldc)  // points at C[m0][n0]
{
    __shared__ __align__(16) float As[GBK * GSTR];
    __shared__ __align__(16) float Bs[GBK * GSTR];

    const int tid = threadIdx.x;          // 256 threads
    const int ty = tid >> 4;              // 0..15  -> rows ty*8..+8
    const int tx = tid & 15;              // 0..15  -> cols tx*8..+8

    float acc[8][8];
#pragma unroll
    for (int i = 0; i < 8; i++)
#pragma unroll
        for (int j = 0; j < 8; j++) acc[i][j] = 0.f;

    for (int k0 = 0; k0 < DMODEL; k0 += GBK) {
#pragma unroll
        for (int l = 0; l < 2; l++) {
            int idx = tid + l * 256;      // 0..511
            int row = idx >> 2;           // 0..127
            int kk  = (idx & 3) << 2;     // 0,4,8,12
            float4 va = *(const float4*)(A + (size_t)row * DMODEL + k0 + kk);
            As[(kk + 0) * GSTR + row] = va.x;
            As[(kk + 1) * GSTR + row] = va.y;
            As[(kk + 2) * GSTR + row] = va.z;
            As[(kk + 3) * GSTR + row] = va.w;
            float4 vb = *(const float4*)(W + (size_t)row * DMODEL + k0 + kk);
            Bs[(kk + 0) * GSTR + row] = vb.x;
            Bs[(kk + 1) * GSTR + row] = vb.y;
            Bs[(kk + 2) * GSTR + row] = vb.z;
            Bs[(kk + 3) * GSTR + row] = vb.w;
        }
        __syncthreads();

#pragma unroll
        for (int k = 0; k < GBK; k++) {
            float a[8], b[8];
            *(float4*)(&a[0]) = *(const float4*)(&As[k * GSTR + ty * 8]);
            *(float4*)(&a[4]) = *(const float4*)(&As[k * GSTR + ty * 8 + 4]);
            *(float4*)(&b[0]) = *(const float4*)(&Bs[k * GSTR + tx * 8]);
            *(float4*)(&b[4]) = *(const float4*)(&Bs[k * GSTR + tx * 8 + 4]);
#pragma unroll
            for (int i = 0; i < 8; i++)
#pragma unroll
                for (int j = 0; j < 8; j++)
                    acc[i][j] = fmaf(a[i], b[j], acc[i][j]);
        }
        __syncthreads();
    }

    // epilogue: add bias, vectorized store
    float bb[8];
    *(float4*)(&bb[0]) = *(const float4*)(&bias[tx * 8]);
    *(float4*)(&bb[4]) = *(const float4*)(&bias[tx * 8 + 4]);
#pragma unroll
    for (int i = 0; i < 8; i++) {
        int m = ty * 8 + i;
#pragma unroll
        for (int j = 0; j < 8; j += 4) {
            float4 o;
            o.x = acc[i][j + 0] + bb[j + 0];
            o.y = acc[i][j + 1] + bb[j + 1];
            o.z = acc[i][j + 2] + bb[j + 2];
            o.w = acc[i][j + 3] + bb[j + 3];
            *(float4*)(&C[(size_t)m * ldc + tx * 8 + j]) = o;
        }
    }
}

// Fused QKV projection: block columns 0..15 -> Q, 16 -> K, 17 -> V
__global__ __launch_bounds__(256) void qkv_kernel(
    const float* __restrict__ X,
    const float* __restrict__ Wq, const float* __restrict__ bq,
    const float* __restrict__ Wk, const float* __restrict__ bk,
    const float* __restrict__ Wv, const float* __restrict__ bv)
{
    int bn = blockIdx.x;   // 0..17
    int bm = blockIdx.y;   // 0..31
    const float* A = X + (size_t)bm * GBM * DMODEL;
    const float* W;
    const float* bias;
    float* C;
    int ldc;
    if (bn < 16) {
        W = Wq + (size_t)bn * GBN * DMODEL;
        bias = bq + bn * GBN;
        C = g_q + (size_t)bm * GBM * DMODEL + bn * GBN;
        ldc = DMODEL;
    } else if (bn == 16) {
        W = Wk; bias = bk;
        C = g_k + (size_t)bm * GBM * HD;
        ldc = HD;
    } else {
        W = Wv; bias = bv;
        C = g_v + (size_t)bm * GBM * HD;
        ldc = HD;
    }
    gemm_tile(A, W, bias, C, ldc);
}

// Output projection over flat (b,h,s,hd) buffer (matches reference's reshape)
__global__ __launch_bounds__(256) void oproj_kernel(
    const float* __restrict__ Wo, const float* __restrict__ bo,
    float* __restrict__ out)
{
    int bn = blockIdx.x;   // 0..15
    int bm = blockIdx.y;   // 0..31
    gemm_tile(g_attn + (size_t)bm * GBM * DMODEL,
              Wo + (size_t)bn * GBN * DMODEL,
              bo + bn * GBN,
              out + (size_t)bm * GBM * DMODEL + bn * GBN,
              DMODEL);
}

// ---------------- Flash-style attention ----------------
// block = (q-tile of 64 rows) x (head) x (batch); 256 threads
// smem: Qs/Ks/Vs 64x128 (stride 132), Ss 64x64 (stride 68), row stats
#define AT_BM 64
#define AT_BN 64
#define ATSTR 132
#define SSTR  68
#define ATT_SMEM_FLOATS (3 * AT_BM * ATSTR + AT_BM * SSTR + 3 * AT_BM)
#define ATT_SMEM_BYTES  (ATT_SMEM_FLOATS * 4)

__global__ __launch_bounds__(256) void attn_kernel()
{
    extern __shared__ __align__(16) float sm[];
    float* Qs = sm;                        // 64*132
    float* Ks = Qs + AT_BM * ATSTR;
    float* Vs = Ks + AT_BM * ATSTR;
    float* Ss = Vs + AT_BM * ATSTR;        // 64*68
    float* mrow = Ss + AT_BM * SSTR;       // 64
    float* lrow = mrow + AT_BM;            // 64
    float* arow = lrow + AT_BM;            // 64

    const int tid = threadIdx.x;
    const int qt = blockIdx.x;             // 0..31
    const int h  = blockIdx.y;             // 0..15
    const int b  = blockIdx.z;             // 0..1

    const float* qbase = g_q + ((size_t)(b * SLEN + qt * AT_BM)) * DMODEL + h * HD;
    const float* kbase = g_k + (size_t)b * SLEN * HD;
    const float* vbase = g_v + (size_t)b * SLEN * HD;

    // load Q tile (64x128)
#pragma unroll
    for (int l = 0; l < 8; l++) {
        int idx = tid + l * 256;
        int row = idx >> 5;
        int d4  = (idx & 31) << 2;
        *(float4*)(&Qs[row * ATSTR + d4]) =
            *(const float4*)(qbase + (size_t)row * DMODEL + d4);
    }
    if (tid < AT_BM) { mrow[tid] = -1e30f; lrow[tid] = 0.f; }

    float o[4][8];
#pragma unroll
    for (int i = 0; i < 4; i++)
#pragma unroll
        for (int j = 0; j < 8; j++) o[i][j] = 0.f;

    const int r0  = (tid >> 4) * 4;   // O / score rows: r0..r0+4
    const int oc  = (tid & 15) * 8;   // O cols: oc..oc+8
    const int cx4 = (tid & 15) * 4;   // score cols: cx4..cx4+4
    const int rr  = tid >> 2;         // softmax row (4 threads/row)
    const int p   = tid & 3;

    const float scale = 0.08838834764831845f; // 1/sqrt(128)

    for (int kt = 0; kt < SLEN / AT_BN; kt++) {
        __syncthreads();  // previous iteration done with Ks/Vs/Ss
        const float* kp = kbase + (size_t)kt * AT_BN * HD;
        const float* vp = vbase + (size_t)kt * AT_BN * HD;
#pragma unroll
        for (int l = 0; l < 8; l++) {
            int idx = tid + l * 256;
            int row = idx >> 5;
            int d4  = (idx & 31) << 2;
            *(float4*)(&Ks[row * ATSTR + d4]) = *(const float4*)(kp + row * HD + d4);
            *(float4*)(&Vs[row * ATSTR + d4]) = *(const float4*)(vp + row * HD + d4);
        }
        __syncthreads();

        // S = Q @ K^T (each thread: 4x4 of the 64x64 tile)
        float sacc[4][4];
#pragma unroll
        for (int i = 0; i < 4; i++)
#pragma unroll
            for (int j = 0; j < 4; j++) sacc[i][j] = 0.f;

#pragma unroll 8
        for (int d = 0; d < HD; d += 4) {
            float4 qv[4], kv[4];
#pragma unroll
            for (int i = 0; i < 4; i++)
                qv[i] = *(const float4*)(&Qs[(r0 + i) * ATSTR + d]);
#pragma unroll
            for (int j = 0; j < 4; j++)
                kv[j] = *(const float4*)(&Ks[(cx4 + j) * ATSTR + d]);
#pragma unroll
            for (int i = 0; i < 4; i++)
#pragma unroll
                for (int j = 0; j < 4; j++)
                    sacc[i][j] += qv[i].x * kv[j].x + qv[i].y * kv[j].y +
                                  qv[i].z * kv[j].z + qv[i].w * kv[j].w;
        }
#pragma unroll
        for (int i = 0; i < 4; i++)
#pragma unroll
            for (int j = 0; j < 4; j++)
                Ss[(r0 + i) * SSTR + cx4 + j] = sacc[i][j] * scale;
        __syncthreads();

        // online softmax (4 threads per row, 16 cols each)
        {
            const int cb = p * 16;
            float mx = -1e30f;
#pragma unroll
            for (int c = 0; c < 16; c++)
                mx = fmaxf(mx, Ss[rr * SSTR + cb + c]);
            mx = fmaxf(mx, __shfl_xor_sync(0xffffffffu, mx, 1));
            mx = fmaxf(mx, __shfl_xor_sync(0xffffffffu, mx, 2));
            float mold = mrow[rr];
            float mnew = fmaxf(mold, mx);
            float sum = 0.f;
#pragma unroll
            for (int c = 0; c < 16; c++) {
                float e = __expf(Ss[rr * SSTR + cb + c] - mnew);
                Ss[rr * SSTR + cb + c] = e;
                sum += e;
            }
            sum += __shfl_xor_sync(0xffffffffu, sum, 1);
            sum += __shfl_xor_sync(0xffffffffu, sum, 2);
            if (p == 0) {
                float al = __expf(mold - mnew);
                arow[rr] = al;
                lrow[rr] = lrow[rr] * al + sum;
                mrow[rr] = mnew;
            }
        }
        __syncthreads();

        // O = O*alpha + P @ V
#pragma unroll
        for (int i = 0; i < 4; i++) {
            float al = arow[r0 + i];
#pragma unroll
            for (int j = 0; j < 8; j++) o[i][j] *= al;
        }
#pragma unroll 4
        for (int c = 0; c < AT_BN; c++) {
            float4 v0 = *(const float4*)(&Vs[c * ATSTR + oc]);
            float4 v1 = *(const float4*)(&Vs[c * ATSTR + oc + 4]);
#pragma unroll
            for (int i = 0; i < 4; i++) {
                float pv = Ss[(r0 + i) * SSTR + c];
                o[i][0] += pv * v0.x; o[i][1] += pv * v0.y;
                o[i][2] += pv * v0.z; o[i][3] += pv * v0.w;
                o[i][4] += pv * v1.x; o[i][5] += pv * v1.y;
                o[i][6] += pv * v1.z; o[i][7] += pv * v1.w;
            }
        }
    }

    // write normalized output in (b, h, s, hd) order
    float* obase = g_attn + ((size_t)((b * NH + h) * SLEN + qt * AT_BM)) * HD;
#pragma unroll
    for (int i = 0; i < 4; i++) {
        int row = r0 + i;
        float inv = 1.f / lrow[row];
        float4 w0, w1;
        w0.x = o[i][0] * inv; w0.y = o[i][1] * inv;
        w0.z = o[i][2] * inv; w0.w = o[i][3] * inv;
        w1.x = o[i][4] * inv; w1.y = o[i][5] * inv;
        w1.z = o[i][6] * inv; w1.w = o[i][7] * inv;
        *(float4*)(&obase[(size_t)row * HD + oc])     = w0;
        *(float4*)(&obase[(size_t)row * HD + oc + 4]) = w1;
    }
}

// ---------------- launch ----------------
extern "C" void kernel_launch(void* const* d_in, const int* in_sizes, int n_in,
                              void* d_out, int out_size)
{
    const float* x  = (const float*)d_in[0];
    const float* Wq = (const float*)d_in[1];
    const float* bq = (const float*)d_in[2];
    const float* Wk = (const float*)d_in[3];
    const float* bk = (const float*)d_in[4];
    const float* Wv = (const float*)d_in[5];
    const float* bv = (const float*)d_in[6];
    const float* Wo = (const float*)d_in[7];
    const float* bo = (const float*)d_in[8];
    float* out = (float*)d_out;

    cudaFuncSetAttribute(attn_kernel,
                         cudaFuncAttributeMaxDynamicSharedMemorySize,
                         ATT_SMEM_BYTES);

    // 1) fused QKV projection: grid (18 col-tiles, 32 row-tiles)
    qkv_kernel<<<dim3(18, 32), 256>>>(x, Wq, bq, Wk, bk, Wv, bv);
    // 2) attention: one block per (64-row q tile, head, batch)
    attn_kernel<<<dim3(SLEN / AT_BM, NH, BDIM), 256, ATT_SMEM_BYTES>>>();
    // 3) output projection
    oproj_kernel<<<dim3(DMODEL / GBN, MROWS / GBM), 256>>>(Wo, bo, out);
}

// round 3
// speedup vs baseline: 3.8377x; 3.8377x over previous
#include <cuda_runtime.h>
#include <cuda_bf16.h>
#include <math.h>
#include <stdint.h>

// Problem constants
#define BDIM   2
#define SLEN   2048
#define DMODEL 2048
#define NH     16
#define HD     128
#define MROWS  (BDIM * SLEN)   // 4096
#define NQKV   2304

// ---------------- scratch (no allocations allowed) ----------------
__device__ __nv_bfloat16 g_xh[(size_t)MROWS * DMODEL];
__device__ __nv_bfloat16 g_xl[(size_t)MROWS * DMODEL];
__device__ __nv_bfloat16 g_wh[(size_t)NQKV * DMODEL];   // [0,2048)=Wq [2048,2176)=Wk [2176,2304)=Wv
__device__ __nv_bfloat16 g_wl[(size_t)NQKV * DMODEL];
__device__ __nv_bfloat16 g_woh[(size_t)DMODEL * DMODEL];
__device__ __nv_bfloat16 g_wol[(size_t)DMODEL * DMODEL];
__device__ __nv_bfloat16 g_qh[(size_t)MROWS * DMODEL];
__device__ __nv_bfloat16 g_ql[(size_t)MROWS * DMODEL];
__device__ __nv_bfloat16 g_kh[(size_t)MROWS * HD];
__device__ __nv_bfloat16 g_kl[(size_t)MROWS * HD];
__device__ __nv_bfloat16 g_vth[(size_t)BDIM * HD * SLEN];  // [b][j][s]
__device__ __nv_bfloat16 g_vtl[(size_t)BDIM * HD * SLEN];
__device__ __nv_bfloat16 g_ah[(size_t)MROWS * DMODEL];     // attn out split, flat (b,h,s,hd)
__device__ __nv_bfloat16 g_al[(size_t)MROWS * DMODEL];

// ---------------- helpers ----------------
__device__ __forceinline__ void mma16816(float c[4],
    uint32_t a0, uint32_t a1, uint32_t a2, uint32_t a3, uint32_t b0, uint32_t b1)
{
    asm volatile(
        "mma.sync.aligned.m16n8k16.row.col.f32.bf16.bf16.f32 "
        "{%0,%1,%2,%3},{%4,%5,%6,%7},{%8,%9},{%0,%1,%2,%3};"
        : "+f"(c[0]), "+f"(c[1]), "+f"(c[2]), "+f"(c[3])
        : "r"(a0), "r"(a1), "r"(a2), "r"(a3), "r"(b0), "r"(b1));
}

__device__ __forceinline__ uint32_t packbf(float x, float y) {
    __nv_bfloat162 t = __floats2bfloat162_rn(x, y);
    return reinterpret_cast<uint32_t&>(t);
}
__device__ __forceinline__ void splitpair(float x, float y, uint32_t& h, uint32_t& l) {
    __nv_bfloat16 hx = __float2bfloat16(x), hy = __float2bfloat16(y);
    h = ((uint32_t)__bfloat16_as_ushort(hy) << 16) | __bfloat16_as_ushort(hx);
    l = packbf(x - __bfloat162float(hx), y - __bfloat162float(hy));
}

// ---------------- fp32 -> bf16 hi/lo split ----------------
__global__ __launch_bounds__(256) void cvt_split_kernel(const float* __restrict__ src,
                                                        __nv_bfloat16* __restrict__ hi,
                                                        __nv_bfloat16* __restrict__ lo, int n4)
{
    int i = blockIdx.x * blockDim.x + threadIdx.x;
    if (i >= n4) return;
    float4 v = ((const float4*)src)[i];
    uint32_t h0, l0, h1, l1;
    splitpair(v.x, v.y, h0, l0);
    splitpair(v.z, v.w, h1, l1);
    uint2 H, L;
    H.x = h0; H.y = h1; L.x = l0; L.y = l1;
    ((uint2*)hi)[i] = H;
    ((uint2*)lo)[i] = L;
}

// ---------------- mma.sync GEMM core: 128x128 block, K=2048 ----------------
#define GSTRIDE 72                  // padded bf16 stride for 64-col chunk
#define GT_ELEMS (128 * GSTRIDE)    // 9216
#define GEMM_SMEM (4 * GT_ELEMS * 2)  // 73728 bytes

__device__ __forceinline__ void gemm_compute(
    const __nv_bfloat16* __restrict__ Ah, const __nv_bfloat16* __restrict__ Al,
    const __nv_bfloat16* __restrict__ Bh, const __nv_bfloat16* __restrict__ Bl,
    float acc[2][8][4])
{
    extern __shared__ __align__(16) __nv_bfloat16 smg[];
    __nv_bfloat16* AhS = smg;
    __nv_bfloat16* AlS = smg + GT_ELEMS;
    __nv_bfloat16* BhS = smg + 2 * GT_ELEMS;
    __nv_bfloat16* BlS = smg + 3 * GT_ELEMS;
    const uint32_t* AhW = (const uint32_t*)AhS;
    const uint32_t* AlW = (const uint32_t*)AlS;
    const uint32_t* BhW = (const uint32_t*)BhS;
    const uint32_t* BlW = (const uint32_t*)BlS;

    const int tid = threadIdx.x, lane = tid & 31, wid = tid >> 5;
    const int wm = wid & 3, wn = wid >> 2;      // warp grid 4(m) x 2(n)
    const int gr = lane >> 2, q4 = lane & 3;

#pragma unroll
    for (int mt = 0; mt < 2; mt++)
#pragma unroll
        for (int nt = 0; nt < 8; nt++)
#pragma unroll
            for (int j = 0; j < 4; j++) acc[mt][nt][j] = 0.f;

    for (int c = 0; c < DMODEL / 64; c++) {
        const size_t k0 = (size_t)c * 64;
        // fill 4 tensors, 128 rows x 64 bf16 each
#pragma unroll
        for (int it = 0; it < 4; it++) {
            int idx = tid + it * 256;          // 0..1023
            int row = idx >> 3, slot = idx & 7;
            size_t go = (size_t)row * DMODEL + k0 + slot * 8;
            int so = row * GSTRIDE + slot * 8;
            *(uint4*)(AhS + so) = *(const uint4*)(Ah + go);
            *(uint4*)(AlS + so) = *(const uint4*)(Al + go);
            *(uint4*)(BhS + so) = *(const uint4*)(Bh + go);
            *(uint4*)(BlS + so) = *(const uint4*)(Bl + go);
        }
        __syncthreads();

#pragma unroll
        for (int ks = 0; ks < 4; ks++) {
            const int ak = ks * 16 + 2 * q4;
            uint32_t aH[2][4], aL[2][4];
#pragma unroll
            for (int mt = 0; mt < 2; mt++) {
                int r = 32 * wm + 16 * mt + gr;
                aH[mt][0] = AhW[(r * GSTRIDE + ak) >> 1];
                aH[mt][1] = AhW[((r + 8) * GSTRIDE + ak) >> 1];
                aH[mt][2] = AhW[(r * GSTRIDE + ak + 8) >> 1];
                aH[mt][3] = AhW[((r + 8) * GSTRIDE + ak + 8) >> 1];
                aL[mt][0] = AlW[(r * GSTRIDE + ak) >> 1];
                aL[mt][1] = AlW[((r + 8) * GSTRIDE + ak) >> 1];
                aL[mt][2] = AlW[(r * GSTRIDE + ak + 8) >> 1];
                aL[mt][3] = AlW[((r + 8) * GSTRIDE + ak + 8) >> 1];
            }
#pragma unroll
            for (int nt = 0; nt < 8; nt++) {
                int col = 64 * wn + 8 * nt + gr;
                uint32_t bh0 = BhW[(col * GSTRIDE + ak) >> 1];
                uint32_t bh1 = BhW[(col * GSTRIDE + ak + 8) >> 1];
                uint32_t bl0 = BlW[(col * GSTRIDE + ak) >> 1];
                uint32_t bl1 = BlW[(col * GSTRIDE + ak + 8) >> 1];
#pragma unroll
                for (int mt = 0; mt < 2; mt++) {
                    mma16816(acc[mt][nt], aH[mt][0], aH[mt][1], aH[mt][2], aH[mt][3], bh0, bh1);
                    mma16816(acc[mt][nt], aL[mt][0], aL[mt][1], aL[mt][2], aL[mt][3], bh0, bh1);
                    mma16816(acc[mt][nt], aH[mt][0], aH[mt][1], aH[mt][2], aH[mt][3], bl0, bl1);
                }
            }
        }
        __syncthreads();
    }
}

// ---------------- QKV projection ----------------
__global__ __launch_bounds__(256) void qkv_mma_kernel(
    const float* __restrict__ bq, const float* __restrict__ bk, const float* __restrict__ bv)
{
    const int bn = blockIdx.x;   // 0..17
    const int bm = blockIdx.y;   // 0..31
    const int m0 = bm * 128;

    const __nv_bfloat16 *Bh, *Bl;
    const float* bias;
    if (bn < 16)       { Bh = g_wh + (size_t)bn * 128 * DMODEL; Bl = g_wl + (size_t)bn * 128 * DMODEL; bias = bq + bn * 128; }
    else if (bn == 16) { Bh = g_wh + (size_t)2048 * DMODEL;     Bl = g_wl + (size_t)2048 * DMODEL;     bias = bk; }
    else               { Bh = g_wh + (size_t)2176 * DMODEL;     Bl = g_wl + (size_t)2176 * DMODEL;     bias = bv; }

    float acc[2][8][4];
    gemm_compute(g_xh + (size_t)m0 * DMODEL, g_xl + (size_t)m0 * DMODEL, Bh, Bl, acc);

    const int lane = threadIdx.x & 31, wid = threadIdx.x >> 5;
    const int wm = wid & 3, wn = wid >> 2;
    const int gr = lane >> 2, q4 = lane & 3;

#pragma unroll
    for (int mt = 0; mt < 2; mt++) {
#pragma unroll
        for (int nt = 0; nt < 8; nt++) {
            int rl = 32 * wm + 16 * mt + gr;
            int cl = 64 * wn + 8 * nt + 2 * q4;
            float bb0 = bias[cl], bb1 = bias[cl + 1];
#pragma unroll
            for (int hf = 0; hf < 2; hf++) {
                int r = rl + 8 * hf;
                float v0 = acc[mt][nt][2 * hf] + bb0;
                float v1 = acc[mt][nt][2 * hf + 1] + bb1;
                if (bn < 16) {
                    uint32_t h, l;
                    splitpair(v0, v1, h, l);
                    size_t o = (size_t)(m0 + r) * DMODEL + bn * 128 + cl;
                    *(uint32_t*)&g_qh[o] = h;
                    *(uint32_t*)&g_ql[o] = l;
                } else if (bn == 16) {
                    uint32_t h, l;
                    splitpair(v0, v1, h, l);
                    size_t o = (size_t)(m0 + r) * HD + cl;
                    *(uint32_t*)&g_kh[o] = h;
                    *(uint32_t*)&g_kl[o] = l;
                } else {
                    // V transposed: g_vt[b][j][s]
                    int mg = m0 + r;
                    int b = mg >> 11, s = mg & 2047;
                    size_t o0 = (size_t)b * HD * SLEN + (size_t)cl * SLEN + s;
                    __nv_bfloat16 h0 = __float2bfloat16(v0);
                    g_vth[o0] = h0;
                    g_vtl[o0] = __float2bfloat16(v0 - __bfloat162float(h0));
                    __nv_bfloat16 h1 = __float2bfloat16(v1);
                    g_vth[o0 + SLEN] = h1;
                    g_vtl[o0 + SLEN] = __float2bfloat16(v1 - __bfloat162float(h1));
                }
            }
        }
    }
}

// ---------------- output projection ----------------
__global__ __launch_bounds__(256) void oproj_mma_kernel(const float* __restrict__ bo,
                                                        float* __restrict__ out)
{
    const int bn = blockIdx.x;   // 0..15
    const int bm = blockIdx.y;   // 0..31
    const int m0 = bm * 128;
    const int n0 = bn * 128;

    float acc[2][8][4];
    gemm_compute(g_ah + (size_t)m0 * DMODEL, g_al + (size_t)m0 * DMODEL,
                 g_woh + (size_t)n0 * DMODEL, g_wol + (size_t)n0 * DMODEL, acc);

    const int lane = threadIdx.x & 31, wid = threadIdx.x >> 5;
    const int wm = wid & 3, wn = wid >> 2;
    const int gr = lane >> 2, q4 = lane & 3;

#pragma unroll
    for (int mt = 0; mt < 2; mt++) {
#pragma unroll
        for (int nt = 0; nt < 8; nt++) {
            int rl = 32 * wm + 16 * mt + gr;
            int cl = 64 * wn + 8 * nt + 2 * q4;
            float bb0 = bo[n0 + cl], bb1 = bo[n0 + cl + 1];
#pragma unroll
            for (int hf = 0; hf < 2; hf++) {
                int r = rl + 8 * hf;
                float2 o2;
                o2.x = acc[mt][nt][2 * hf] + bb0;
                o2.y = acc[mt][nt][2 * hf + 1] + bb1;
                *(float2*)&out[(size_t)(m0 + r) * DMODEL + n0 + cl] = o2;
            }
        }
    }
}

// ---------------- attention (FA2-style mma.sync) ----------------
#define QSTR 136
#define KSTR 136
#define VSTR 72
#define OFF_QH 0
#define OFF_QL (128 * QSTR)
#define OFF_KH (2 * 128 * QSTR)
#define OFF_KL (OFF_KH + 64 * KSTR)
#define OFF_VH (OFF_KH + 2 * 64 * KSTR)
#define OFF_VL (OFF_VH + 128 * VSTR)
#define ATT_SMEM ((OFF_VL + 128 * VSTR) * 2)   // 141312 bytes

__global__ __launch_bounds__(256) void attn_mma_kernel()
{
    extern __shared__ __align__(16) __nv_bfloat16 sm[];
    const int tid = threadIdx.x, lane = tid & 31, w = tid >> 5;
    const int qt = blockIdx.x, h = blockIdx.y, b = blockIdx.z;
    const int q0 = qt * 128;
    const int gr = lane >> 2, q4 = lane & 3;

    // load Q tile (128 x 128, hi+lo)
    const __nv_bfloat16* qsH = g_qh + ((size_t)(b * SLEN + q0)) * DMODEL + h * HD;
    const __nv_bfloat16* qsL = g_ql + ((size_t)(b * SLEN + q0)) * DMODEL + h * HD;
#pragma unroll
    for (int it = 0; it < 8; it++) {
        int idx = tid + it * 256;
        int row = idx >> 4, slot = idx & 15;
        size_t go = (size_t)row * DMODEL + slot * 8;
        *(uint4*)(sm + OFF_QH + row * QSTR + slot * 8) = *(const uint4*)(qsH + go);
        *(uint4*)(sm + OFF_QL + row * QSTR + slot * 8) = *(const uint4*)(qsL + go);
    }

    const __nv_bfloat16* kbH = g_kh + (size_t)b * SLEN * HD;
    const __nv_bfloat16* kbL = g_kl + (size_t)b * SLEN * HD;
    const __nv_bfloat16* vbH = g_vth + (size_t)b * HD * SLEN;
    const __nv_bfloat16* vbL = g_vtl + (size_t)b * HD * SLEN;

    const uint32_t* QHW = (const uint32_t*)(sm + OFF_QH);
    const uint32_t* QLW = (const uint32_t*)(sm + OFF_QL);
    const uint32_t* KHW = (const uint32_t*)(sm + OFF_KH);
    const uint32_t* KLW = (const uint32_t*)(sm + OFF_KL);
    const uint32_t* VHW = (const uint32_t*)(sm + OFF_VH);
    const uint32_t* VLW = (const uint32_t*)(sm + OFF_VL);

    float oacc[16][4];
#pragma unroll
    for (int nt = 0; nt < 16; nt++)
#pragma unroll
        for (int j = 0; j < 4; j++) oacc[nt][j] = 0.f;

    float m0 = -1e30f, m1 = -1e30f, l0 = 0.f, l1 = 0.f;
    const float scale = 0.08838834764831845f;   // 1/sqrt(128)
    const int qrow = 16 * w + gr;

    for (int kt = 0; kt < SLEN / 64; kt++) {
        __syncthreads();   // previous iteration done with K/V smem
#pragma unroll
        for (int it = 0; it < 4; it++) {
            int idx = tid + it * 256;
            { // K tile: 64 rows x 128
                int row = idx >> 4, slot = idx & 15;
                size_t go = (size_t)(kt * 64 + row) * HD + slot * 8;
                *(uint4*)(sm + OFF_KH + row * KSTR + slot * 8) = *(const uint4*)(kbH + go);
                *(uint4*)(sm + OFF_KL + row * KSTR + slot * 8) = *(const uint4*)(kbL + go);
            }
            { // Vt tile: 128 rows x 64
                int row = idx >> 3, slot = idx & 7;
                size_t go = (size_t)row * SLEN + kt * 64 + slot * 8;
                *(uint4*)(sm + OFF_VH + row * VSTR + slot * 8) = *(const uint4*)(vbH + go);
                *(uint4*)(sm + OFF_VL + row * VSTR + slot * 8) = *(const uint4*)(vbL + go);
            }
        }
        __syncthreads();

        // S = Q @ K^T  (warp: 16 q-rows x 64 keys)
        float sacc[8][4];
#pragma unroll
        for (int nt = 0; nt < 8; nt++)
#pragma unroll
            for (int j = 0; j < 4; j++) sacc[nt][j] = 0.f;

#pragma unroll
        for (int ks = 0; ks < 8; ks++) {
            const int ak = ks * 16 + 2 * q4;
            uint32_t aH0 = QHW[(qrow * QSTR + ak) >> 1];
            uint32_t aH1 = QHW[((qrow + 8) * QSTR + ak) >> 1];
            uint32_t aH2 = QHW[(qrow * QSTR + ak + 8) >> 1];
            uint32_t aH3 = QHW[((qrow + 8) * QSTR + ak + 8) >> 1];
            uint32_t aL0 = QLW[(qrow * QSTR + ak) >> 1];
            uint32_t aL1 = QLW[((qrow + 8) * QSTR + ak) >> 1];
            uint32_t aL2 = QLW[(qrow * QSTR + ak + 8) >> 1];
            uint32_t aL3 = QLW[((qrow + 8) * QSTR + ak + 8) >> 1];
#pragma unroll
            for (int nt = 0; nt < 8; nt++) {
                int kc = 8 * nt + gr;
                uint32_t bh0 = KHW[(kc * KSTR + ak) >> 1];
                uint32_t bh1 = KHW[(kc * KSTR + ak + 8) >> 1];
                uint32_t bl0 = KLW[(kc * KSTR + ak) >> 1];
                uint32_t bl1 = KLW[(kc * KSTR + ak + 8) >> 1];
                mma16816(sacc[nt], aH0, aH1, aH2, aH3, bh0, bh1);
                mma16816(sacc[nt], aL0, aL1, aL2, aL3, bh0, bh1);
                mma16816(sacc[nt], aH0, aH1, aH2, aH3, bl0, bl1);
            }
        }

        // online softmax on the two row-halves
        float mx0 = -1e30f, mx1 = -1e30f;
#pragma unroll
        for (int nt = 0; nt < 8; nt++) {
            sacc[nt][0] *= scale; sacc[nt][1] *= scale;
            sacc[nt][2] *= scale; sacc[nt][3] *= scale;
            mx0 = fmaxf(mx0, fmaxf(sacc[nt][0], sacc[nt][1]));
            mx1 = fmaxf(mx1, fmaxf(sacc[nt][2], sacc[nt][3]));
        }
        mx0 = fmaxf(mx0, __shfl_xor_sync(0xffffffffu, mx0, 1));
        mx0 = fmaxf(mx0, __shfl_xor_sync(0xffffffffu, mx0, 2));
        mx1 = fmaxf(mx1, __shfl_xor_sync(0xffffffffu, mx1, 1));
        mx1 = fmaxf(mx1, __shfl_xor_sync(0xffffffffu, mx1, 2));
        float mn0 = fmaxf(m0, mx0), mn1 = fmaxf(m1, mx1);
        float al0 = __expf(m0 - mn0), al1 = __expf(m1 - mn1);

        float s0 = 0.f, s1 = 0.f;
        uint32_t pH[8], pL[8], pH2[8], pL2[8];
#pragma unroll
        for (int nt = 0; nt < 8; nt++) {
            float p0 = __expf(sacc[nt][0] - mn0);
            float p1 = __expf(sacc[nt][1] - mn0);
            float p2 = __expf(sacc[nt][2] - mn1);
            float p3 = __expf(sacc[nt][3] - mn1);
            s0 += p0 + p1; s1 += p2 + p3;
            splitpair(p0, p1, pH[nt], pL[nt]);
            splitpair(p2, p3, pH2[nt], pL2[nt]);
        }
        s0 += __shfl_xor_sync(0xffffffffu, s0, 1);
        s0 += __shfl_xor_sync(0xffffffffu, s0, 2);
        s1 += __shfl_xor_sync(0xffffffffu, s1, 1);
        s1 += __shfl_xor_sync(0xffffffffu, s1, 2);
        l0 = l0 * al0 + s0;
        l1 = l1 * al1 + s1;
        m0 = mn0; m1 = mn1;

#pragma unroll
        for (int nt = 0; nt < 16; nt++) {
            oacc[nt][0] *= al0; oacc[nt][1] *= al0;
            oacc[nt][2] *= al1; oacc[nt][3] *= al1;
        }

        // O += P @ V
#pragma unroll
        for (int kc = 0; kc < 4; kc++) {
            uint32_t aH0 = pH[2 * kc], aH1 = pH2[2 * kc], aH2 = pH[2 * kc + 1], aH3 = pH2[2 * kc + 1];
            uint32_t aL0 = pL[2 * kc], aL1 = pL2[2 * kc], aL2 = pL[2 * kc + 1], aL3 = pL2[2 * kc + 1];
            const int vk = kc * 16 + 2 * q4;
#pragma unroll
            for (int nt = 0; nt < 16; nt++) {
                int j = 8 * nt + gr;
                uint32_t bh0 = VHW[(j * VSTR + vk) >> 1];
                uint32_t bh1 = VHW[(j * VSTR + vk + 8) >> 1];
                uint32_t bl0 = VLW[(j * VSTR + vk) >> 1];
                uint32_t bl1 = VLW[(j * VSTR + vk + 8) >> 1];
                mma16816(oacc[nt], aH0, aH1, aH2, aH3, bh0, bh1);
                mma16816(oacc[nt], aL0, aL1, aL2, aL3, bh0, bh1);
                mma16816(oacc[nt], aH0, aH1, aH2, aH3, bl0, bl1);
            }
        }
    }

    // normalize + write split bf16 to flat (b,h,s,hd)
    float i0 = 1.f / l0, i1 = 1.f / l1;
    size_t rg = (size_t)((b * NH + h) * SLEN + q0 + qrow);
#pragma unroll
    for (int nt = 0; nt < 16; nt++) {
        int col = 8 * nt + 2 * q4;
        uint32_t hh, ll;
        splitpair(oacc[nt][0] * i0, oacc[nt][1] * i0, hh, ll);
        *(uint32_t*)&g_ah[rg * HD + col] = hh;
        *(uint32_t*)&g_al[rg * HD + col] = ll;
        splitpair(oacc[nt][2] * i1, oacc[nt][3] * i1, hh, ll);
        *(uint32_t*)&g_ah[(rg + 8) * HD + col] = hh;
        *(uint32_t*)&g_al[(rg + 8) * HD + col] = ll;
    }
}

// ---------------- launch ----------------
extern "C" void kernel_launch(void* const* d_in, const int* in_sizes, int n_in,
                              void* d_out, int out_size)
{
    const float* x  = (const float*)d_in[0];
    const float* Wq = (const float*)d_in[1];
    const float* bq = (const float*)d_in[2];
    const float* Wk = (const float*)d_in[3];
    const float* bk = (const float*)d_in[4];
    const float* Wv = (const float*)d_in[5];
    const float* bv = (const float*)d_in[6];
    const float* Wo = (const float*)d_in[7];
    const float* bo = (const float*)d_in[8];
    float* out = (float*)d_out;

    cudaFuncSetAttribute(qkv_mma_kernel,   cudaFuncAttributeMaxDynamicSharedMemorySize, GEMM_SMEM);
    cudaFuncSetAttribute(oproj_mma_kernel, cudaFuncAttributeMaxDynamicSharedMemorySize, GEMM_SMEM);
    cudaFuncSetAttribute(attn_mma_kernel,  cudaFuncAttributeMaxDynamicSharedMemorySize, ATT_SMEM);

    __nv_bfloat16 *xh, *xl, *wh, *wl, *woh, *wol;
    cudaGetSymbolAddress((void**)&xh,  g_xh);
    cudaGetSymbolAddress((void**)&xl,  g_xl);
    cudaGetSymbolAddress((void**)&wh,  g_wh);
    cudaGetSymbolAddress((void**)&wl,  g_wl);
    cudaGetSymbolAddress((void**)&woh, g_woh);
    cudaGetSymbolAddress((void**)&wol, g_wol);

    // fp32 -> bf16 hi/lo splits (inputs + weights)
    {
        int n4 = (MROWS * DMODEL) / 4;
        cvt_split_kernel<<<(n4 + 255) / 256, 256>>>(x, xh, xl, n4);
        n4 = (DMODEL * DMODEL) / 4;
        cvt_split_kernel<<<(n4 + 255) / 256, 256>>>(Wq, wh, wl, n4);
        n4 = (HD * DMODEL) / 4;
        cvt_split_kernel<<<(n4 + 255) / 256, 256>>>(Wk, wh + (size_t)2048 * DMODEL, wl + (size_t)2048 * DMODEL, n4);
        cvt_split_kernel<<<(n4 + 255) / 256, 256>>>(Wv, wh + (size_t)2176 * DMODEL, wl + (size_t)2176 * DMODEL, n4);
        n4 = (DMODEL * DMODEL) / 4;
        cvt_split_kernel<<<(n4 + 255) / 256, 256>>>(Wo, woh, wol, n4);
    }

    // 1) fused QKV projection (mma.sync tensor cores)
    qkv_mma_kernel<<<dim3(18, 32), 256, GEMM_SMEM>>>(bq, bk, bv);
    // 2) attention (mma.sync)
    attn_mma_kernel<<<dim3(SLEN / 128, NH, BDIM), 256, ATT_SMEM>>>();
    // 3) output projection
    oproj_mma_kernel<<<dim3(16, 32), 256, GEMM_SMEM>>>(bo, out);
}